// round 9
// baseline (speedup 1.0000x reference)
#include <cuda_runtime.h>
#include <cstdint>

#define NV 8192
#define NC 128

typedef signed char s8;

// -------------------- device scratch (no allocs allowed) --------------------
__device__ s8 g_Eh [(size_t)NV * NV];   // E row-major, hi int8
__device__ s8 g_El [(size_t)NV * NV];
__device__ s8 g_ETh[(size_t)NV * NV];   // E^T row-major, hi int8
__device__ s8 g_ETl[(size_t)NV * NV];
__device__ s8 g_xqh[NC * NV], g_xql[NC * NV];   // xw^T quantized [C][V]
__device__ s8 g_yqh[NC * NV], g_yql[NC * NV];   // y^T  quantized [C][V]
__device__ float g_tmpT[NC * NV];               // fp32 staging (xw^T, then y^T)
__device__ float g_part[2][NV * NC];            // split-K partials
__device__ float g_E0[64 * NC];
__device__ float g_E1[128 * NC];
__device__ unsigned g_maxE, g_maxX, g_maxY;     // float bits (non-negative)

// -------------------- helpers ------------------------------------------------
__device__ __forceinline__ void quant15(float v, float inv, s8& h, s8& l) {
    int q = __float2int_rn(v * inv);      // |q| <= 16221 by scale choice
    int hh = (q + 64) >> 7;               // h in [-127, 127]
    h = (s8)hh;
    l = (s8)(q - (hh << 7));              // l in [-64, 63]
}
__device__ __forceinline__ float scale_of(unsigned bits) {
    return 1.01f * __uint_as_float(bits) + 1e-30f;
}
__device__ __forceinline__ void block_max_commit(float m, unsigned* dst) {
    __shared__ float wmax[8];
#pragma unroll
    for (int o = 16; o > 0; o >>= 1)
        m = fmaxf(m, __shfl_xor_sync(0xffffffff, m, o));
    int t = threadIdx.x + threadIdx.y * blockDim.x;
    if ((t & 31) == 0) wmax[t >> 5] = m;
    __syncthreads();
    if (t == 0) {
        float bm = wmax[0];
        int nw = (blockDim.x * blockDim.y) >> 5;
        for (int i = 1; i < nw; i++) bm = fmaxf(bm, wmax[i]);
        atomicMax(dst, __float_as_uint(bm));
    }
}

// -------------------- small kernels ------------------------------------------
__global__ void init_kernel() { g_maxE = 0; g_maxX = 0; g_maxY = 0; }

__global__ void coef_kernel(const float* __restrict__ ev0,
                            const float* __restrict__ ev1,
                            const float* __restrict__ dt) {
    int c = threadIdx.x;
    int b = blockIdx.x;
    if (b < 64) g_E0[b * NC + c] = __expf(-ev0[b] * dt[c]);
    else        g_E1[(b - 64) * NC + c] = __expf(-ev1[b - 64] * dt[NC + c]);
}

__global__ void __launch_bounds__(256) maxE_kernel(const float4* __restrict__ E4) {
    float m = 0.0f;
    const size_t n4 = (size_t)NV * NV / 4;
    for (size_t i = (size_t)blockIdx.x * 256 + threadIdx.x; i < n4;
         i += (size_t)gridDim.x * 256) {
        float4 v = E4[i];
        m = fmaxf(m, fmaxf(fmaxf(fabsf(v.x), fabsf(v.y)), fmaxf(fabsf(v.z), fabsf(v.w))));
    }
    block_max_commit(m, &g_maxE);
}

// E fp32 -> int8 hi/lo, both orientations (32x32 tiles, smem transpose)
__global__ void __launch_bounds__(256) convE_kernel(const float* __restrict__ E) {
    __shared__ float t[32][33];
    const float inv = 16384.0f / scale_of(g_maxE);
    const int r0 = blockIdx.y * 32, c0 = blockIdx.x * 32;
    const int tx = threadIdx.x, ty = threadIdx.y;
#pragma unroll
    for (int k = 0; k < 4; k++)
        t[ty + 8 * k][tx] = E[(size_t)(r0 + ty + 8 * k) * NV + c0 + tx];
    __syncthreads();
#pragma unroll
    for (int k = 0; k < 4; k++) {
        s8 h, l;
        quant15(t[ty + 8 * k][tx], inv, h, l);
        size_t a = (size_t)(r0 + ty + 8 * k) * NV + c0 + tx;
        g_Eh[a] = h; g_El[a] = l;
        quant15(t[tx][ty + 8 * k], inv, h, l);
        size_t b = (size_t)(c0 + ty + 8 * k) * NV + r0 + tx;
        g_ETh[b] = h; g_ETl[b] = l;
    }
}

// xw = x*mass, write transposed fp32 [C][V] + global max
__global__ void __launch_bounds__(256) prepx_kernel(const float* __restrict__ x,
                                                    const float* __restrict__ mass) {
    __shared__ float t[32][33];
    const int v0 = blockIdx.x * 32, c0 = blockIdx.y * 32;
    const int tx = threadIdx.x, ty = threadIdx.y;
    float m = 0.0f;
#pragma unroll
    for (int k = 0; k < 4; k++) {
        int v = v0 + ty + 8 * k;
        float val = x[(size_t)v * NC + c0 + tx] * mass[v];
        t[ty + 8 * k][tx] = val;
        m = fmaxf(m, fabsf(val));
    }
    __syncthreads();
#pragma unroll
    for (int k = 0; k < 4; k++)
        g_tmpT[(size_t)(c0 + ty + 8 * k) * NV + v0 + tx] = t[tx][ty + 8 * k];
    block_max_commit(m, &g_maxX);
}

// quantize fp32 [C][V] -> int8 hi/lo (4 values per thread, packed stores)
__global__ void __launch_bounds__(256) quantT_kernel(const float4* __restrict__ src,
                                                     uint32_t* __restrict__ h4,
                                                     uint32_t* __restrict__ l4,
                                                     const unsigned* __restrict__ maxp) {
    const float inv = 16384.0f / scale_of(*maxp);
    int idx = blockIdx.x * 256 + threadIdx.x;     // over NC*NV/4
    float4 v = src[idx];
    s8 h0, h1, h2, h3, l0, l1, l2, l3;
    quant15(v.x, inv, h0, l0);
    quant15(v.y, inv, h1, l1);
    quant15(v.z, inv, h2, l2);
    quant15(v.w, inv, h3, l3);
    h4[idx] = (uint32_t)(uint8_t)h0 | ((uint32_t)(uint8_t)h1 << 8) |
              ((uint32_t)(uint8_t)h2 << 16) | ((uint32_t)(uint8_t)h3 << 24);
    l4[idx] = (uint32_t)(uint8_t)l0 | ((uint32_t)(uint8_t)l1 << 8) |
              ((uint32_t)(uint8_t)l2 << 16) | ((uint32_t)(uint8_t)l3 << 24);
}

// reduce GEMM1 partials, apply scales + coef, write y^T fp32 [C][V] + max
__global__ void __launch_bounds__(256) reduce1_kernel(const float* __restrict__ P0,
                                                      const float* __restrict__ P1) {
    __shared__ float t[32][33];
    const float sc = scale_of(g_maxE) * scale_of(g_maxX) * (1.0f / 268435456.0f);
    const int v0 = blockIdx.x * 32, c0 = blockIdx.y * 32;
    const int tx = threadIdx.x, ty = threadIdx.y;
    float m = 0.0f;
#pragma unroll
    for (int k = 0; k < 4; k++) {
        int v = v0 + ty + 8 * k, c = c0 + tx;
        size_t a = (size_t)v * NC + c;
        float y = sc * (P0[a] + P1[a]) * g_E0[(v >> 7) * NC + c] * g_E1[(v & 127) * NC + c];
        t[ty + 8 * k][tx] = y;
        m = fmaxf(m, fabsf(y));
    }
    __syncthreads();
#pragma unroll
    for (int k = 0; k < 4; k++)
        g_tmpT[(size_t)(c0 + ty + 8 * k) * NV + v0 + tx] = t[tx][ty + 8 * k];
    block_max_commit(m, &g_maxY);
}

// reduce GEMM2 partials -> fp32 out [V][C]
__global__ void __launch_bounds__(256) reduce2_kernel(const float4* __restrict__ P0,
                                                      const float4* __restrict__ P1,
                                                      float4* __restrict__ out) {
    const float sc = scale_of(g_maxE) * scale_of(g_maxY) * (1.0f / 268435456.0f);
    int idx = blockIdx.x * 256 + threadIdx.x;
    float4 a = P0[idx], b = P1[idx];
    out[idx] = make_float4(sc * (a.x + b.x), sc * (a.y + b.y),
                           sc * (a.z + b.z), sc * (a.w + b.w));
}

// -------------------- IMMA GEMM ------------------------------------------------
__device__ __forceinline__ void ldsm4(uint32_t* r, uint32_t addr) {
    asm volatile("ldmatrix.sync.aligned.m8n8.x4.shared.b16 {%0,%1,%2,%3}, [%4];"
                 : "=r"(r[0]), "=r"(r[1]), "=r"(r[2]), "=r"(r[3]) : "r"(addr));
}
__device__ __forceinline__ void imma16832(int* d, const uint32_t* a,
                                          uint32_t b0, uint32_t b1) {
    asm volatile("mma.sync.aligned.m16n8k32.row.col.s32.s8.s8.s32 "
                 "{%0,%1,%2,%3}, {%4,%5,%6,%7}, {%8,%9}, {%0,%1,%2,%3};"
                 : "+r"(d[0]), "+r"(d[1]), "+r"(d[2]), "+r"(d[3])
                 : "r"(a[0]), "r"(a[1]), "r"(a[2]), "r"(a[3]), "r"(b0), "r"(b1));
}
#define CP16(dst, src) \
    asm volatile("cp.async.cg.shared.global [%0], [%1], 16;" :: "r"(dst), "l"(src) : "memory")

// Tile: BM=64 (m) x BN=128 (n) x BK=64 (k bytes). Warps 2(m) x 4(n), warp tile 32x32.
// A: [m][k] int8 row-major (hi+lo). B: [n][k] int8 row-major (hi+lo).
// D_raw = 16384*sum(h*h) + 128*sum(h*l + l*h)   (ll dropped)
#define APITCH 80                       // 64 data + 16 pad bytes
#define A_BYTES (64 * APITCH)           // 5120
#define B_BYTES (128 * APITCH)          // 10240
#define STAGE (2 * A_BYTES + 2 * B_BYTES)  // 30720
#define GSMEM (2 * STAGE)               // 61440 -> 2 CTAs/SM

__global__ void __launch_bounds__(256, 2)
gemm_s8(const s8* __restrict__ Ah, const s8* __restrict__ Al,
        const s8* __restrict__ Bh, const s8* __restrict__ Bl,
        float* __restrict__ P)
{
    extern __shared__ char sm[];
    const uint32_t smbase = (uint32_t)__cvta_generic_to_shared(sm);
    const int tid  = threadIdx.x;
    const int lane = tid & 31, wid = tid >> 5;
    const int wm   = wid >> 2, wn = wid & 3;
    const int m0   = blockIdx.x * 64;
    const int kbase = blockIdx.y * (NV / 2);
    float* Pout = P + (size_t)blockIdx.y * NV * NC;

    auto issue = [&](int kt, int s) {
        const int k0 = kbase + kt * 64;
        const uint32_t sb = smbase + s * STAGE;
        {   // A: 64 rows x 4 chunks = 256
            int r = tid >> 2, q = tid & 3;
            size_t ga = (size_t)(m0 + r) * NV + k0 + q * 16;
            uint32_t so = sb + (uint32_t)(r * APITCH + q * 16);
            CP16(so, (const void*)(Ah + ga));
            CP16(so + A_BYTES, (const void*)(Al + ga));
        }
#pragma unroll
        for (int i = 0; i < 2; i++) {   // B: 128 rows x 4 chunks = 512
            int idx = i * 256 + tid;
            int r = idx >> 2, q = idx & 3;
            size_t gb = (size_t)r * NV + k0 + q * 16;
            uint32_t so = sb + 2 * A_BYTES + (uint32_t)(r * APITCH + q * 16);
            CP16(so, (const void*)(Bh + gb));
            CP16(so + B_BYTES, (const void*)(Bl + gb));
        }
        asm volatile("cp.async.commit_group;" ::: "memory");
    };

    int accA[2][4][4], accB[2][4][4];
#pragma unroll
    for (int a = 0; a < 2; a++)
#pragma unroll
        for (int b = 0; b < 4; b++)
#pragma unroll
            for (int q = 0; q < 4; q++) { accA[a][b][q] = 0; accB[a][b][q] = 0; }

    auto compute = [&](int s) {
        const uint32_t Ab = smbase + s * STAGE;
        const uint32_t Bb = Ab + 2 * A_BYTES;
#pragma unroll
        for (int ks = 0; ks < 2; ks++) {           // two k32 steps per ktile
            uint32_t ah[2][4], al[2][4], bhf[2][4], blf[2][4];
#pragma unroll
            for (int mi = 0; mi < 2; mi++) {
                uint32_t addr = Ab + (uint32_t)((wm * 32 + mi * 16 + (lane & 15)) * APITCH
                                 + ks * 32 + ((lane >> 4) << 4));
                ldsm4(ah[mi], addr);
                ldsm4(al[mi], addr + A_BYTES);
            }
#pragma unroll
            for (int nb = 0; nb < 2; nb++) {
                uint32_t addr = Bb + (uint32_t)((wn * 32 + nb * 16 + (lane & 15)) * APITCH
                                 + ks * 32 + ((lane >> 4) << 4));
                ldsm4(bhf[nb], addr);
                ldsm4(blf[nb], addr + B_BYTES);
            }
#pragma unroll
            for (int mi = 0; mi < 2; mi++)
#pragma unroll
                for (int nj = 0; nj < 4; nj++)
                    imma16832(accA[mi][nj], ah[mi],
                              bhf[nj >> 1][nj & 1], bhf[nj >> 1][(nj & 1) + 2]);
#pragma unroll
            for (int mi = 0; mi < 2; mi++)
#pragma unroll
                for (int nj = 0; nj < 4; nj++)
                    imma16832(accB[mi][nj], ah[mi],
                              blf[nj >> 1][nj & 1], blf[nj >> 1][(nj & 1) + 2]);
#pragma unroll
            for (int mi = 0; mi < 2; mi++)
#pragma unroll
                for (int nj = 0; nj < 4; nj++)
                    imma16832(accB[mi][nj], al[mi],
                              bhf[nj >> 1][nj & 1], bhf[nj >> 1][(nj & 1) + 2]);
        }
    };

    const int NIT = (NV / 2) / 64;   // 64
    issue(0, 0);
#pragma unroll 1
    for (int kt = 0; kt < NIT; kt++) {
        asm volatile("cp.async.wait_group 0;" ::: "memory");
        __syncthreads();
        if (kt + 1 < NIT) issue(kt + 1, (kt + 1) & 1);
        compute(kt & 1);
        __syncthreads();
    }

    // epilogue: raw combined fp32 partial
#pragma unroll
    for (int mi = 0; mi < 2; mi++) {
#pragma unroll
        for (int q = 0; q < 2; q++) {
            int gm = m0 + wm * 32 + mi * 16 + (lane >> 2) + q * 8;
#pragma unroll
            for (int nj = 0; nj < 4; nj++) {
                int gn = wn * 32 + nj * 8 + (lane & 3) * 2;
                float v0 = 16384.0f * (float)accA[mi][nj][q * 2 + 0]
                         +   128.0f * (float)accB[mi][nj][q * 2 + 0];
                float v1 = 16384.0f * (float)accA[mi][nj][q * 2 + 1]
                         +   128.0f * (float)accB[mi][nj][q * 2 + 1];
                *(float2*)&Pout[(size_t)gm * NC + gn] = make_float2(v0, v1);
            }
        }
    }
}

// -------------------- launch -----------------------------------------------------
// Inputs: 0:x[V,C] 1:edge_index 2:L 3:mass[V] 4:evals0[64] 5:evals1[128]
//         6:evecs[V,V] 7:diffusion_time[2,C]   Output: [V,C] fp32
extern "C" void kernel_launch(void* const* d_in, const int* in_sizes, int n_in,
                              void* d_out, int out_size) {
    const float* x      = (const float*)d_in[0];
    const float* mass   = (const float*)d_in[3];
    const float* evals0 = (const float*)d_in[4];
    const float* evals1 = (const float*)d_in[5];
    const float* evecs  = (const float*)d_in[6];
    const float* dt     = (const float*)d_in[7];
    float* out          = (float*)d_out;

    s8 *Eh, *El, *ETh, *ETl, *xqh, *xql, *yqh, *yql;
    float *tmpT, *P;
    unsigned *mX, *mY;
    cudaGetSymbolAddress((void**)&Eh,   g_Eh);
    cudaGetSymbolAddress((void**)&El,   g_El);
    cudaGetSymbolAddress((void**)&ETh,  g_ETh);
    cudaGetSymbolAddress((void**)&ETl,  g_ETl);
    cudaGetSymbolAddress((void**)&xqh,  g_xqh);
    cudaGetSymbolAddress((void**)&xql,  g_xql);
    cudaGetSymbolAddress((void**)&yqh,  g_yqh);
    cudaGetSymbolAddress((void**)&yql,  g_yql);
    cudaGetSymbolAddress((void**)&tmpT, g_tmpT);
    cudaGetSymbolAddress((void**)&P,    g_part);
    cudaGetSymbolAddress((void**)&mX,   g_maxX);
    cudaGetSymbolAddress((void**)&mY,   g_maxY);

    cudaFuncSetAttribute(gemm_s8, cudaFuncAttributeMaxDynamicSharedMemorySize, GSMEM);

    init_kernel<<<1, 1>>>();
    maxE_kernel<<<1184, 256>>>((const float4*)evecs);
    coef_kernel<<<192, 128>>>(evals0, evals1, dt);
    convE_kernel<<<dim3(256, 256), dim3(32, 8)>>>(evecs);
    prepx_kernel<<<dim3(256, 4), dim3(32, 8)>>>(x, mass);
    quantT_kernel<<<NC * NV / 4 / 256, 256>>>((const float4*)tmpT,
                                              (uint32_t*)xqh, (uint32_t*)xql, mX);

    // GEMM1: raw(E^T @ xw), split-K
    gemm_s8<<<dim3(NV / 64, 2), 256, GSMEM>>>(ETh, ETl, xqh, xql, P);
    reduce1_kernel<<<dim3(256, 4), dim3(32, 8)>>>(P, P + NV * NC);
    quantT_kernel<<<NC * NV / 4 / 256, 256>>>((const float4*)tmpT,
                                              (uint32_t*)yqh, (uint32_t*)yql, mY);
    // GEMM2: raw(E @ y), split-K
    gemm_s8<<<dim3(NV / 64, 2), 256, GSMEM>>>(Eh, El, yqh, yql, P);
    reduce2_kernel<<<NV * NC / 4 / 256, 256>>>((const float4*)P,
                                               (const float4*)(P + NV * NC),
                                               (float4*)out);
}

// round 10
// speedup vs baseline: 2.5662x; 2.5662x over previous
#include <cuda_runtime.h>
#include <cuda_bf16.h>
#include <cstdint>

#define NV 8192
#define NC 128

// -------------------- device scratch (no allocs allowed) --------------------
__device__ __nv_bfloat16 g_xh[NV * NC];
__device__ __nv_bfloat16 g_xl[NV * NC];
__device__ __nv_bfloat16 g_yh[NV * NC];
__device__ __nv_bfloat16 g_yl[NV * NC];
__device__ float g_E0[64 * NC];
__device__ float g_E1[128 * NC];

// -------------------- small kernels ------------------------------------------
__global__ void coef_kernel(const float* __restrict__ ev0,
                            const float* __restrict__ ev1,
                            const float* __restrict__ dt) {
    int c = threadIdx.x;
    int b = blockIdx.x;
    if (b < 64) g_E0[b * NC + c] = __expf(-ev0[b] * dt[c]);
    else        g_E1[(b - 64) * NC + c] = __expf(-ev1[b - 64] * dt[NC + c]);
}

__device__ __forceinline__ uint32_t pack_bf2(__nv_bfloat16 a, __nv_bfloat16 b) {
    __nv_bfloat162 p{a, b};
    return *(uint32_t*)&p;
}

__global__ void __launch_bounds__(256) prepx_kernel(const float4* __restrict__ x4,
                                                    const float* __restrict__ mass,
                                                    uint2* __restrict__ xh,
                                                    uint2* __restrict__ xl) {
    int idx = blockIdx.x * 256 + threadIdx.x;
    float m = mass[(idx * 4) >> 7];
    float4 v = x4[idx];
    float a = v.x * m, b = v.y * m, c = v.z * m, d = v.w * m;
    __nv_bfloat16 h0 = __float2bfloat16(a), h1 = __float2bfloat16(b);
    __nv_bfloat16 h2 = __float2bfloat16(c), h3 = __float2bfloat16(d);
    __nv_bfloat16 l0 = __float2bfloat16(a - __bfloat162float(h0));
    __nv_bfloat16 l1 = __float2bfloat16(b - __bfloat162float(h1));
    __nv_bfloat16 l2 = __float2bfloat16(c - __bfloat162float(h2));
    __nv_bfloat16 l3 = __float2bfloat16(d - __bfloat162float(h3));
    xh[idx] = make_uint2(pack_bf2(h0, h1), pack_bf2(h2, h3));
    xl[idx] = make_uint2(pack_bf2(l0, l1), pack_bf2(l2, l3));
}

// -------------------- mma.sync helpers ----------------------------------------
__device__ __forceinline__ void ldsm4t(uint32_t* r, uint32_t addr) {
    asm volatile("ldmatrix.sync.aligned.m8n8.x4.trans.shared.b16 {%0,%1,%2,%3}, [%4];"
                 : "=r"(r[0]), "=r"(r[1]), "=r"(r[2]), "=r"(r[3]) : "r"(addr));
}
__device__ __forceinline__ void mma16816(float* d, const uint32_t* a, const uint32_t* b) {
    asm volatile("mma.sync.aligned.m16n8k16.row.col.f32.bf16.bf16.f32 "
                 "{%0,%1,%2,%3}, {%4,%5,%6,%7}, {%8,%9}, {%0,%1,%2,%3};"
                 : "+f"(d[0]), "+f"(d[1]), "+f"(d[2]), "+f"(d[3])
                 : "r"(a[0]), "r"(a[1]), "r"(a[2]), "r"(a[3]),
                   "r"(b[0]), "r"(b[1]));
}
#define CP16(dst, src) \
    asm volatile("cp.async.cg.shared.global [%0], [%1], 16;" :: "r"(dst), "l"(src) : "memory")

// fp32 pair -> bf16 hi (truncation, via PRMT) + bf16 lo (exact residual, rounded)
__device__ __forceinline__ void split_pair(float v0, float v1, uint32_t& h, uint32_t& l) {
    uint32_t u0 = __float_as_uint(v0), u1 = __float_as_uint(v1);
    h = __byte_perm(u0, u1, 0x7632);                       // {hi16(v0), hi16(v1)}
    float l0 = v0 - __uint_as_float(u0 & 0xFFFF0000u);
    float l1 = v1 - __uint_as_float(u1 & 0xFFFF0000u);
    asm("cvt.rn.bf16x2.f32 %0, %1, %2;" : "=r"(l) : "f"(l1), "f"(l0));
}

// -------------------- GEMM config ----------------------------------------------
// BM=64, BN=128, BK=64. Warps 2(M) x 4(N), warp tile 32x32.
// A: fp32 E tile, converted to bf16 hi/lo in-register at fragment load.
//   TRANS_A=1: tile [64 k-rows][64 m-cols], pitch 68 floats (LDS.32 conflict-free)
//   TRANS_A=0: tile [64 m-rows][64 k-cols], pitch 72 floats (LDS.64 conflict-free)
// B: bf16 hi/lo pre-split, [k][n] rows, pitch 136 halves.
#define BM 64
#define BK 64
#define BPAD 136
#define B_BYTES (BK * BPAD * 2)          // 17408

template <int TRANS_A>
struct Cfg {
    static constexpr int APITCH  = TRANS_A ? 68 : 72;       // floats
    static constexpr int A_BYTES = 64 * APITCH * 4;         // 17408 / 18432
    static constexpr int STAGE   = A_BYTES + 2 * B_BYTES;   // 52224 / 53248
    static constexpr int NSTAGE  = 3;
    static constexpr int SMEM    = NSTAGE * STAGE;          // <= 159744
};

template <int TRANS_A, int EPI>
__global__ void __launch_bounds__(256, 1)
gemm_kernel(const float* __restrict__ A,
            const __nv_bfloat16* __restrict__ Bhi, const __nv_bfloat16* __restrict__ Blo,
            float* __restrict__ C,
            __nv_bfloat16* __restrict__ yhi, __nv_bfloat16* __restrict__ ylo,
            const float* __restrict__ E0, const float* __restrict__ E1)
{
    using CF = Cfg<TRANS_A>;
    extern __shared__ char sm[];
    const uint32_t smbase = (uint32_t)__cvta_generic_to_shared(sm);
    const int tid  = threadIdx.x;
    const int lane = tid & 31, wid = tid >> 5;
    const int wm   = wid >> 2, wn = wid & 3;      // 2 x 4 warps (32x32 tiles)
    const int m0   = blockIdx.x * BM;

    auto issue = [&](int kt, int s) {
        const int k0 = kt * BK;
        const uint32_t sb = smbase + s * CF::STAGE;
        // A: 64 rows x 16 chunks of 16B = 1024 -> 4 per thread
#pragma unroll
        for (int i = 0; i < 4; i++) {
            int idx = i * 256 + tid;
            int r = idx >> 4, q = idx & 15;
            size_t ga = TRANS_A ? (size_t)(k0 + r) * NV + m0 + q * 4
                                : (size_t)(m0 + r) * NV + k0 + q * 4;
            CP16(sb + (uint32_t)(r * CF::APITCH * 4 + q * 16), (const void*)(A + ga));
        }
        // B: 64 rows x 16 chunks, hi + lo
#pragma unroll
        for (int i = 0; i < 4; i++) {
            int idx = i * 256 + tid;
            int r = idx >> 4, q = idx & 15;
            size_t gb = (size_t)(k0 + r) * NC + q * 8;
            uint32_t so = sb + CF::A_BYTES + (uint32_t)(r * BPAD + q * 8) * 2;
            CP16(so, (const void*)(Bhi + gb));
            CP16(so + B_BYTES, (const void*)(Blo + gb));
        }
        asm volatile("cp.async.commit_group;" ::: "memory");
    };

    float acc[2][4][4];
#pragma unroll
    for (int a = 0; a < 2; a++)
#pragma unroll
        for (int b = 0; b < 4; b++)
#pragma unroll
            for (int q = 0; q < 4; q++) acc[a][b][q] = 0.0f;

    const int rr = lane >> 2;            // 0..7
    const int cc = (lane & 3) * 2;       // 0,2,4,6

    auto compute = [&](int s) {
        const float* As = (const float*)(sm + (size_t)s * CF::STAGE);
        const uint32_t Bhb = smbase + s * CF::STAGE + CF::A_BYTES;
#pragma unroll
        for (int ks = 0; ks < 4; ks++) {
            // ---- A fragments: LDS fp32 + in-register hi/lo split ----
            uint32_t ah[2][4], al[2][4];
#pragma unroll
            for (int mi = 0; mi < 2; mi++) {
                const int mb = wm * 32 + mi * 16 + rr;
                const int kb = ks * 16 + cc;
                float v00, v01, v10, v11, v20, v21, v30, v31;
                if (TRANS_A) {           // tile [k][m], pitch 68
                    v00 = As[(kb    ) * 68 + mb];
                    v01 = As[(kb + 1) * 68 + mb];
                    v10 = As[(kb    ) * 68 + mb + 8];
                    v11 = As[(kb + 1) * 68 + mb + 8];
                    v20 = As[(kb + 8) * 68 + mb];
                    v21 = As[(kb + 9) * 68 + mb];
                    v30 = As[(kb + 8) * 68 + mb + 8];
                    v31 = As[(kb + 9) * 68 + mb + 8];
                } else {                 // tile [m][k], pitch 72
                    float2 p0 = *(const float2*)&As[(mb    ) * 72 + kb];
                    float2 p1 = *(const float2*)&As[(mb + 8) * 72 + kb];
                    float2 p2 = *(const float2*)&As[(mb    ) * 72 + kb + 8];
                    float2 p3 = *(const float2*)&As[(mb + 8) * 72 + kb + 8];
                    v00 = p0.x; v01 = p0.y; v10 = p1.x; v11 = p1.y;
                    v20 = p2.x; v21 = p2.y; v30 = p3.x; v31 = p3.y;
                }
                split_pair(v00, v01, ah[mi][0], al[mi][0]);
                split_pair(v10, v11, ah[mi][1], al[mi][1]);
                split_pair(v20, v21, ah[mi][2], al[mi][2]);
                split_pair(v30, v31, ah[mi][3], al[mi][3]);
            }
            // ---- B fragments: ldmatrix.trans ----
            uint32_t bh[2][4], bl[2][4];
#pragma unroll
            for (int nj2 = 0; nj2 < 2; nj2++) {
                int krow = ks * 16 + (lane & 15);
                int ncol = wn * 32 + nj2 * 16 + ((lane >> 4) << 3);
                uint32_t addr = Bhb + (uint32_t)(krow * BPAD + ncol) * 2;
                ldsm4t(bh[nj2], addr);
                ldsm4t(bl[nj2], addr + B_BYTES);
            }
            // ---- 3 term-major sweeps of 8 independent accumulators ----
#pragma unroll
            for (int mi = 0; mi < 2; mi++)
#pragma unroll
                for (int nj = 0; nj < 4; nj++)
                    mma16816(acc[mi][nj], ah[mi], &bh[nj >> 1][(nj & 1) * 2]);
#pragma unroll
            for (int mi = 0; mi < 2; mi++)
#pragma unroll
                for (int nj = 0; nj < 4; nj++)
                    mma16816(acc[mi][nj], ah[mi], &bl[nj >> 1][(nj & 1) * 2]);
#pragma unroll
            for (int mi = 0; mi < 2; mi++)
#pragma unroll
                for (int nj = 0; nj < 4; nj++)
                    mma16816(acc[mi][nj], al[mi], &bh[nj >> 1][(nj & 1) * 2]);
        }
    };

    const int NIT = NV / BK;   // 128
    issue(0, 0);
    issue(1, 1);
#pragma unroll 1
    for (int kt = 0; kt < NIT; kt++) {
        if (kt < NIT - 1) asm volatile("cp.async.wait_group 1;" ::: "memory");
        else              asm volatile("cp.async.wait_group 0;" ::: "memory");
        __syncthreads();
        compute(kt % CF::NSTAGE);
        if (kt + 2 < NIT) issue(kt + 2, (kt + 2) % CF::NSTAGE);
    }

    // ---- epilogue ----
#pragma unroll
    for (int mi = 0; mi < 2; mi++) {
#pragma unroll
        for (int q = 0; q < 2; q++) {
            int gm = m0 + wm * 32 + mi * 16 + (lane >> 2) + q * 8;
            int i0 = gm >> 7, i1 = gm & 127;
#pragma unroll
            for (int nj = 0; nj < 4; nj++) {
                int gn = wn * 32 + nj * 8 + (lane & 3) * 2;
                float v0 = acc[mi][nj][q * 2 + 0];
                float v1 = acc[mi][nj][q * 2 + 1];
                if (EPI) {
                    v0 *= E0[i0 * NC + gn]     * E1[i1 * NC + gn];
                    v1 *= E0[i0 * NC + gn + 1] * E1[i1 * NC + gn + 1];
                    __nv_bfloat16 h0 = __float2bfloat16(v0);
                    __nv_bfloat16 h1 = __float2bfloat16(v1);
                    __nv_bfloat16 l0 = __float2bfloat16(v0 - __bfloat162float(h0));
                    __nv_bfloat16 l1 = __float2bfloat16(v1 - __bfloat162float(h1));
                    *(uint32_t*)&yhi[(size_t)gm * NC + gn] = pack_bf2(h0, h1);
                    *(uint32_t*)&ylo[(size_t)gm * NC + gn] = pack_bf2(l0, l1);
                } else {
                    *(float2*)&C[(size_t)gm * NC + gn] = make_float2(v0, v1);
                }
            }
        }
    }
}

// -------------------- launch -----------------------------------------------------
// Inputs: 0:x[V,C] 1:edge_index 2:L 3:mass[V] 4:evals0[64] 5:evals1[128]
//         6:evecs[V,V] 7:diffusion_time[2,C]   Output: [V,C] fp32
extern "C" void kernel_launch(void* const* d_in, const int* in_sizes, int n_in,
                              void* d_out, int out_size) {
    const float* x      = (const float*)d_in[0];
    const float* mass   = (const float*)d_in[3];
    const float* evals0 = (const float*)d_in[4];
    const float* evals1 = (const float*)d_in[5];
    const float* evecs  = (const float*)d_in[6];
    const float* dt     = (const float*)d_in[7];
    float* out          = (float*)d_out;

    __nv_bfloat16 *xh, *xl, *yh, *yl;
    float *E0, *E1;
    cudaGetSymbolAddress((void**)&xh, g_xh);
    cudaGetSymbolAddress((void**)&xl, g_xl);
    cudaGetSymbolAddress((void**)&yh, g_yh);
    cudaGetSymbolAddress((void**)&yl, g_yl);
    cudaGetSymbolAddress((void**)&E0, g_E0);
    cudaGetSymbolAddress((void**)&E1, g_E1);

    cudaFuncSetAttribute(gemm_kernel<1, 1>, cudaFuncAttributeMaxDynamicSharedMemorySize, Cfg<1>::SMEM);
    cudaFuncSetAttribute(gemm_kernel<0, 0>, cudaFuncAttributeMaxDynamicSharedMemorySize, Cfg<0>::SMEM);

    coef_kernel<<<192, 128>>>(evals0, evals1, dt);
    prepx_kernel<<<NV * NC / 4 / 256, 256>>>((const float4*)x, mass, (uint2*)xh, (uint2*)xl);

    // GEMM1: y = coef .* (E^T @ xw)  — A = evecs fp32, split in-register
    gemm_kernel<1, 1><<<NV / BM, 256, Cfg<1>::SMEM>>>(evecs, xh, xl,
                                                      nullptr, yh, yl, E0, E1);
    // GEMM2: out = E @ y
    gemm_kernel<0, 0><<<NV / BM, 256, Cfg<0>::SMEM>>>(evecs, yh, yl,
                                                      out, nullptr, nullptr, nullptr, nullptr);
}

// round 11
// speedup vs baseline: 3.3852x; 1.3191x over previous
#include <cuda_runtime.h>
#include <cuda_fp16.h>
#include <cstdint>

#define NV 8192
#define NC 128
#define ESCALE 1024.0f
#define INV_ESCALE 0.0009765625f

// -------------------- device scratch (no allocs allowed) --------------------
__device__ __half g_Eh[(size_t)NV * NV];   // E*1024 hi, row-major
__device__ __half g_El[(size_t)NV * NV];   // E*1024 lo
__device__ __half g_x[NV * NC];            // xw fp16 (single term)
__device__ __half g_y[NV * NC];            // y  fp16 (single term)
__device__ float g_E0[64 * NC];
__device__ float g_E1[128 * NC];

// -------------------- small kernels ------------------------------------------
__global__ void coef_kernel(const float* __restrict__ ev0,
                            const float* __restrict__ ev1,
                            const float* __restrict__ dt) {
    int c = threadIdx.x;
    int b = blockIdx.x;
    if (b < 64) g_E0[b * NC + c] = __expf(-ev0[b] * dt[c]);
    else        g_E1[(b - 64) * NC + c] = __expf(-ev1[b - 64] * dt[NC + c]);
}

__device__ __forceinline__ uint32_t pack_h2(__half a, __half b) {
    __half2 p{a, b};
    return *(uint32_t*)&p;
}

// E fp32 -> fp16 hi/lo of E*1024 (row-major only; ldmatrix.trans gives E^T)
__global__ void __launch_bounds__(256) convE_kernel(const float4* __restrict__ E4,
                                                    uint2* __restrict__ Eh,
                                                    uint2* __restrict__ El) {
    const size_t N4 = (size_t)NV * NV / 4;
    for (size_t idx = (size_t)blockIdx.x * 256 + threadIdx.x; idx < N4;
         idx += (size_t)gridDim.x * 256) {
        float4 v = E4[idx];
        float a = v.x * ESCALE, b = v.y * ESCALE, c = v.z * ESCALE, d = v.w * ESCALE;
        __half h0 = __float2half(a), h1 = __float2half(b);
        __half h2 = __float2half(c), h3 = __float2half(d);
        __half l0 = __float2half(a - __half2float(h0));
        __half l1 = __float2half(b - __half2float(h1));
        __half l2 = __float2half(c - __half2float(h2));
        __half l3 = __float2half(d - __half2float(h3));
        Eh[idx] = make_uint2(pack_h2(h0, h1), pack_h2(h2, h3));
        El[idx] = make_uint2(pack_h2(l0, l1), pack_h2(l2, l3));
    }
}

// xw = x * mass -> single fp16
__global__ void __launch_bounds__(256) prepx_kernel(const float4* __restrict__ x4,
                                                    const float* __restrict__ mass,
                                                    uint2* __restrict__ xq) {
    int idx = blockIdx.x * 256 + threadIdx.x;
    float m = mass[(idx * 4) >> 7];
    float4 v = x4[idx];
    xq[idx] = make_uint2(pack_h2(__float2half(v.x * m), __float2half(v.y * m)),
                         pack_h2(__float2half(v.z * m), __float2half(v.w * m)));
}

// -------------------- mma.sync helpers ----------------------------------------
__device__ __forceinline__ void ldsm4(uint32_t* r, uint32_t addr) {
    asm volatile("ldmatrix.sync.aligned.m8n8.x4.shared.b16 {%0,%1,%2,%3}, [%4];"
                 : "=r"(r[0]), "=r"(r[1]), "=r"(r[2]), "=r"(r[3]) : "r"(addr));
}
__device__ __forceinline__ void ldsm4t(uint32_t* r, uint32_t addr) {
    asm volatile("ldmatrix.sync.aligned.m8n8.x4.trans.shared.b16 {%0,%1,%2,%3}, [%4];"
                 : "=r"(r[0]), "=r"(r[1]), "=r"(r[2]), "=r"(r[3]) : "r"(addr));
}
__device__ __forceinline__ void mma16816(float* d, const uint32_t* a, const uint32_t* b) {
    asm volatile("mma.sync.aligned.m16n8k16.row.col.f32.f16.f16.f32 "
                 "{%0,%1,%2,%3}, {%4,%5,%6,%7}, {%8,%9}, {%0,%1,%2,%3};"
                 : "+f"(d[0]), "+f"(d[1]), "+f"(d[2]), "+f"(d[3])
                 : "r"(a[0]), "r"(a[1]), "r"(a[2]), "r"(a[3]),
                   "r"(b[0]), "r"(b[1]));
}
#define CP16(dst, src) \
    asm volatile("cp.async.cg.shared.global [%0], [%1], 16;" :: "r"(dst), "l"(src) : "memory")

// -------------------- GEMM config ----------------------------------------------
#define BM 64
#define BK 64
#define APAD 72                       // halves/row (144 B stride, mod128=16)
#define BPAD 136
#define A_HALVES (BK * APAD)
#define B_HALVES (BK * BPAD)
#define A_BYTES  (A_HALVES * 2)       // 9216
#define B_BYTES  (B_HALVES * 2)       // 17408
#define STAGE_BYTES (2 * A_BYTES + B_BYTES)   // Ah, Al, B(single) = 35840
#define NSTAGE 3
#define SMEM_BYTES (NSTAGE * STAGE_BYTES)     // 107520

// C[m,n] = sum_k Aop[m,k]*B[k,n]; A = (1024*E) fp16 2-term, B fp16 1-term.
// C_raw = 1024 * true; epilogues divide by 1024.
// TRANS_A=1: Aop[m,k]=E[k,m] (ldmatrix.trans). EPI=1: y=coef*acc/1024 -> fp16.
template <int TRANS_A, int EPI>
__global__ void __launch_bounds__(256, 1)
gemm_kernel(const __half* __restrict__ Ahi, const __half* __restrict__ Alo,
            const __half* __restrict__ B,
            float* __restrict__ C, __half* __restrict__ yout,
            const float* __restrict__ E0, const float* __restrict__ E1)
{
    extern __shared__ __half sm[];
    const uint32_t smbase = (uint32_t)__cvta_generic_to_shared(sm);
    const int tid  = threadIdx.x;
    const int lane = tid & 31, wid = tid >> 5;
    const int wm   = wid >> 2, wn = wid & 3;      // 2 x 4 warps (32x32 tiles)
    const int m0   = blockIdx.x * BM;

    auto issue = [&](int kt, int s) {
        const int k0 = kt * BK;
        const uint32_t sb = smbase + s * STAGE_BYTES;
#pragma unroll
        for (int i = 0; i < 2; i++) {             // A hi+lo: 512 chunks each
            int idx = i * 256 + tid;
            int r = idx >> 3, q = idx & 7;
            size_t ga = TRANS_A ? (size_t)(k0 + r) * NV + m0 + q * 8
                                : (size_t)(m0 + r) * NV + k0 + q * 8;
            uint32_t so = sb + (uint32_t)(r * APAD + q * 8) * 2;
            CP16(so, (const void*)(Ahi + ga));
            CP16(so + A_BYTES, (const void*)(Alo + ga));
        }
#pragma unroll
        for (int i = 0; i < 4; i++) {             // B single: 1024 chunks
            int idx = i * 256 + tid;
            int r = idx >> 4, q = idx & 15;
            size_t gb = (size_t)(k0 + r) * NC + q * 8;
            uint32_t so = sb + 2 * A_BYTES + (uint32_t)(r * BPAD + q * 8) * 2;
            CP16(so, (const void*)(B + gb));
        }
        asm volatile("cp.async.commit_group;" ::: "memory");
    };

    float acc[2][4][4];
#pragma unroll
    for (int a = 0; a < 2; a++)
#pragma unroll
        for (int b = 0; b < 4; b++)
#pragma unroll
            for (int q = 0; q < 4; q++) acc[a][b][q] = 0.0f;

    auto compute = [&](int s) {
        const uint32_t Ahb = smbase + s * STAGE_BYTES;
        const uint32_t Bb  = Ahb + 2 * A_BYTES;
#pragma unroll
        for (int ks = 0; ks < 4; ks++) {
            uint32_t ah[2][4], al[2][4], bf[2][4];
#pragma unroll
            for (int mi = 0; mi < 2; mi++) {
                uint32_t addr;
                if (TRANS_A) {
                    int krow = ks * 16 + (lane & 7) + ((lane >> 4) << 3);
                    int mcol = wm * 32 + mi * 16 + (lane & 8);
                    addr = Ahb + (uint32_t)(krow * APAD + mcol) * 2;
                    ldsm4t(ah[mi], addr);
                    ldsm4t(al[mi], addr + A_BYTES);
                } else {
                    int mrow = wm * 32 + mi * 16 + (lane & 15);
                    int kcol = ks * 16 + ((lane >> 4) << 3);
                    addr = Ahb + (uint32_t)(mrow * APAD + kcol) * 2;
                    ldsm4(ah[mi], addr);
                    ldsm4(al[mi], addr + A_BYTES);
                }
            }
#pragma unroll
            for (int nj2 = 0; nj2 < 2; nj2++) {
                int krow = ks * 16 + (lane & 15);
                int ncol = wn * 32 + nj2 * 16 + ((lane >> 4) << 3);
                ldsm4t(bf[nj2], Bb + (uint32_t)(krow * BPAD + ncol) * 2);
            }
            // 2 term-major sweeps of 8 independent accumulators
#pragma unroll
            for (int mi = 0; mi < 2; mi++)
#pragma unroll
                for (int nj = 0; nj < 4; nj++)
                    mma16816(acc[mi][nj], ah[mi], &bf[nj >> 1][(nj & 1) * 2]);
#pragma unroll
            for (int mi = 0; mi < 2; mi++)
#pragma unroll
                for (int nj = 0; nj < 4; nj++)
                    mma16816(acc[mi][nj], al[mi], &bf[nj >> 1][(nj & 1) * 2]);
        }
    };

    const int NIT = NV / BK;   // 128
    issue(0, 0);
    issue(1, 1);
#pragma unroll 1
    for (int kt = 0; kt < NIT; kt++) {
        if (kt < NIT - 1) asm volatile("cp.async.wait_group 1;" ::: "memory");
        else              asm volatile("cp.async.wait_group 0;" ::: "memory");
        __syncthreads();
        compute(kt % NSTAGE);
        if (kt + 2 < NIT) issue(kt + 2, (kt + 2) % NSTAGE);
    }

    // ---- epilogue ----
#pragma unroll
    for (int mi = 0; mi < 2; mi++) {
#pragma unroll
        for (int q = 0; q < 2; q++) {
            int gm = m0 + wm * 32 + mi * 16 + (lane >> 2) + q * 8;
            int i0 = gm >> 7, i1 = gm & 127;
#pragma unroll
            for (int nj = 0; nj < 4; nj++) {
                int gn = wn * 32 + nj * 8 + (lane & 3) * 2;
                float v0 = acc[mi][nj][q * 2 + 0] * INV_ESCALE;
                float v1 = acc[mi][nj][q * 2 + 1] * INV_ESCALE;
                if (EPI) {
                    v0 *= E0[i0 * NC + gn]     * E1[i1 * NC + gn];
                    v1 *= E0[i0 * NC + gn + 1] * E1[i1 * NC + gn + 1];
                    *(uint32_t*)&yout[(size_t)gm * NC + gn] =
                        pack_h2(__float2half(v0), __float2half(v1));
                } else {
                    *(float2*)&C[(size_t)gm * NC + gn] = make_float2(v0, v1);
                }
            }
        }
    }
}

// -------------------- launch -----------------------------------------------------
// Inputs: 0:x[V,C] 1:edge_index 2:L 3:mass[V] 4:evals0[64] 5:evals1[128]
//         6:evecs[V,V] 7:diffusion_time[2,C]   Output: [V,C] fp32
extern "C" void kernel_launch(void* const* d_in, const int* in_sizes, int n_in,
                              void* d_out, int out_size) {
    const float* x      = (const float*)d_in[0];
    const float* mass   = (const float*)d_in[3];
    const float* evals0 = (const float*)d_in[4];
    const float* evals1 = (const float*)d_in[5];
    const float* evecs  = (const float*)d_in[6];
    const float* dt     = (const float*)d_in[7];
    float* out          = (float*)d_out;

    __half *Eh, *El, *xq, *yq;
    float *E0, *E1;
    cudaGetSymbolAddress((void**)&Eh, g_Eh);
    cudaGetSymbolAddress((void**)&El, g_El);
    cudaGetSymbolAddress((void**)&xq, g_x);
    cudaGetSymbolAddress((void**)&yq, g_y);
    cudaGetSymbolAddress((void**)&E0, g_E0);
    cudaGetSymbolAddress((void**)&E1, g_E1);

    cudaFuncSetAttribute(gemm_kernel<1, 1>, cudaFuncAttributeMaxDynamicSharedMemorySize, SMEM_BYTES);
    cudaFuncSetAttribute(gemm_kernel<0, 0>, cudaFuncAttributeMaxDynamicSharedMemorySize, SMEM_BYTES);

    coef_kernel<<<192, 128>>>(evals0, evals1, dt);
    convE_kernel<<<2368, 256>>>((const float4*)evecs, (uint2*)Eh, (uint2*)El);
    prepx_kernel<<<NV * NC / 4 / 256, 256>>>((const float4*)x, mass, (uint2*)xq);

    // GEMM1: y = coef .* (E^T @ xw)
    gemm_kernel<1, 1><<<NV / BM, 256, SMEM_BYTES>>>(Eh, El, xq,
                                                    nullptr, yq, E0, E1);
    // GEMM2: out = E @ y
    gemm_kernel<0, 0><<<NV / BM, 256, SMEM_BYTES>>>(Eh, El, yq,
                                                    out, nullptr, nullptr, nullptr);
}

// round 12
// speedup vs baseline: 4.9512x; 1.4626x over previous
#include <cuda_runtime.h>
#include <cuda_fp16.h>
#include <cstdint>

#define NV 8192
#define NC 128

// -------------------- device scratch (no allocs allowed) --------------------
__device__ __half g_Eh[(size_t)NV * NV];   // E fp16, row-major
__device__ __half g_x[NV * NC];            // xw fp16
__device__ __half g_y[NV * NC];            // y  fp16
__device__ float g_E0[64 * NC];
__device__ float g_E1[128 * NC];

// -------------------- small kernels ------------------------------------------
__global__ void coef_kernel(const float* __restrict__ ev0,
                            const float* __restrict__ ev1,
                            const float* __restrict__ dt) {
    int c = threadIdx.x;
    int b = blockIdx.x;
    if (b < 64) g_E0[b * NC + c] = __expf(-ev0[b] * dt[c]);
    else        g_E1[(b - 64) * NC + c] = __expf(-ev1[b - 64] * dt[NC + c]);
}

__device__ __forceinline__ uint32_t pack_h2(__half a, __half b) {
    __half2 p{a, b};
    return *(uint32_t*)&p;
}

// E fp32 -> fp16 (row-major; ldmatrix.trans provides E^T inside GEMM1)
__global__ void __launch_bounds__(256) convE_kernel(const float4* __restrict__ E4,
                                                    uint2* __restrict__ Eh) {
    const size_t N4 = (size_t)NV * NV / 4;
    for (size_t idx = (size_t)blockIdx.x * 256 + threadIdx.x; idx < N4;
         idx += (size_t)gridDim.x * 256) {
        float4 v = E4[idx];
        Eh[idx] = make_uint2(pack_h2(__float2half(v.x), __float2half(v.y)),
                             pack_h2(__float2half(v.z), __float2half(v.w)));
    }
}

// xw = x * mass -> fp16
__global__ void __launch_bounds__(256) prepx_kernel(const float4* __restrict__ x4,
                                                    const float* __restrict__ mass,
                                                    uint2* __restrict__ xq) {
    int idx = blockIdx.x * 256 + threadIdx.x;
    float m = mass[(idx * 4) >> 7];
    float4 v = x4[idx];
    xq[idx] = make_uint2(pack_h2(__float2half(v.x * m), __float2half(v.y * m)),
                         pack_h2(__float2half(v.z * m), __float2half(v.w * m)));
}

// -------------------- mma.sync helpers ----------------------------------------
__device__ __forceinline__ void ldsm4(uint32_t* r, uint32_t addr) {
    asm volatile("ldmatrix.sync.aligned.m8n8.x4.shared.b16 {%0,%1,%2,%3}, [%4];"
                 : "=r"(r[0]), "=r"(r[1]), "=r"(r[2]), "=r"(r[3]) : "r"(addr));
}
__device__ __forceinline__ void ldsm4t(uint32_t* r, uint32_t addr) {
    asm volatile("ldmatrix.sync.aligned.m8n8.x4.trans.shared.b16 {%0,%1,%2,%3}, [%4];"
                 : "=r"(r[0]), "=r"(r[1]), "=r"(r[2]), "=r"(r[3]) : "r"(addr));
}
__device__ __forceinline__ void mma16816(float* d, const uint32_t* a, const uint32_t* b) {
    asm volatile("mma.sync.aligned.m16n8k16.row.col.f32.f16.f16.f32 "
                 "{%0,%1,%2,%3}, {%4,%5,%6,%7}, {%8,%9}, {%0,%1,%2,%3};"
                 : "+f"(d[0]), "+f"(d[1]), "+f"(d[2]), "+f"(d[3])
                 : "r"(a[0]), "r"(a[1]), "r"(a[2]), "r"(a[3]),
                   "r"(b[0]), "r"(b[1]));
}
#define CP16(dst, src) \
    asm volatile("cp.async.cg.shared.global [%0], [%1], 16;" :: "r"(dst), "l"(src) : "memory")

// -------------------- GEMM config ----------------------------------------------
#define BM 64
#define BK 64
#define APAD 72                       // halves/row (144 B stride, mod128=16)
#define BPAD 136
#define A_BYTES  (BK * APAD * 2)      // 9216
#define B_BYTES  (BK * BPAD * 2)      // 17408
#define STAGE_BYTES (A_BYTES + B_BYTES)   // 26624
#define NSTAGE 4
#define SMEM_BYTES (NSTAGE * STAGE_BYTES) // 106496

// C[m,n] = sum_k Aop[m,k]*B[k,n]; plain fp16 single-term.
// TRANS_A=1: Aop[m,k]=E[k,m] (ldmatrix.trans). EPI=1: y=coef*acc -> fp16.
template <int TRANS_A, int EPI>
__global__ void __launch_bounds__(256, 1)
gemm_kernel(const __half* __restrict__ A, const __half* __restrict__ B,
            float* __restrict__ C, __half* __restrict__ yout,
            const float* __restrict__ E0, const float* __restrict__ E1)
{
    extern __shared__ __half sm[];
    const uint32_t smbase = (uint32_t)__cvta_generic_to_shared(sm);
    const int tid  = threadIdx.x;
    const int lane = tid & 31, wid = tid >> 5;
    const int wm   = wid >> 2, wn = wid & 3;      // 2 x 4 warps (32x32 tiles)
    const int m0   = blockIdx.x * BM;

    auto issue = [&](int kt, int s) {
        const int k0 = kt * BK;
        const uint32_t sb = smbase + s * STAGE_BYTES;
#pragma unroll
        for (int i = 0; i < 2; i++) {             // A: 512 chunks
            int idx = i * 256 + tid;
            int r = idx >> 3, q = idx & 7;
            size_t ga = TRANS_A ? (size_t)(k0 + r) * NV + m0 + q * 8
                                : (size_t)(m0 + r) * NV + k0 + q * 8;
            CP16(sb + (uint32_t)(r * APAD + q * 8) * 2, (const void*)(A + ga));
        }
#pragma unroll
        for (int i = 0; i < 4; i++) {             // B: 1024 chunks
            int idx = i * 256 + tid;
            int r = idx >> 4, q = idx & 15;
            size_t gb = (size_t)(k0 + r) * NC + q * 8;
            CP16(sb + A_BYTES + (uint32_t)(r * BPAD + q * 8) * 2, (const void*)(B + gb));
        }
        asm volatile("cp.async.commit_group;" ::: "memory");
    };

    float acc[2][4][4];
#pragma unroll
    for (int a = 0; a < 2; a++)
#pragma unroll
        for (int b = 0; b < 4; b++)
#pragma unroll
            for (int q = 0; q < 4; q++) acc[a][b][q] = 0.0f;

    auto compute = [&](int s) {
        const uint32_t Ab = smbase + s * STAGE_BYTES;
        const uint32_t Bb = Ab + A_BYTES;
#pragma unroll
        for (int ks = 0; ks < 4; ks++) {
            uint32_t af[2][4], bf[2][4];
#pragma unroll
            for (int mi = 0; mi < 2; mi++) {
                if (TRANS_A) {
                    int krow = ks * 16 + (lane & 7) + ((lane >> 4) << 3);
                    int mcol = wm * 32 + mi * 16 + (lane & 8);
                    ldsm4t(af[mi], Ab + (uint32_t)(krow * APAD + mcol) * 2);
                } else {
                    int mrow = wm * 32 + mi * 16 + (lane & 15);
                    int kcol = ks * 16 + ((lane >> 4) << 3);
                    ldsm4(af[mi], Ab + (uint32_t)(mrow * APAD + kcol) * 2);
                }
            }
#pragma unroll
            for (int nj2 = 0; nj2 < 2; nj2++) {
                int krow = ks * 16 + (lane & 15);
                int ncol = wn * 32 + nj2 * 16 + ((lane >> 4) << 3);
                ldsm4t(bf[nj2], Bb + (uint32_t)(krow * BPAD + ncol) * 2);
            }
#pragma unroll
            for (int mi = 0; mi < 2; mi++)
#pragma unroll
                for (int nj = 0; nj < 4; nj++)
                    mma16816(acc[mi][nj], af[mi], &bf[nj >> 1][(nj & 1) * 2]);
        }
    };

    const int NIT = NV / BK;   // 128
    issue(0, 0);
    issue(1, 1);
    issue(2, 2);
#pragma unroll 1
    for (int kt = 0; kt < NIT; kt++) {
        if (kt < NIT - 2)      asm volatile("cp.async.wait_group 2;" ::: "memory");
        else if (kt < NIT - 1) asm volatile("cp.async.wait_group 1;" ::: "memory");
        else                   asm volatile("cp.async.wait_group 0;" ::: "memory");
        __syncthreads();
        compute(kt % NSTAGE);
        if (kt + 3 < NIT) issue(kt + 3, (kt + 3) % NSTAGE);
    }

    // ---- epilogue ----
#pragma unroll
    for (int mi = 0; mi < 2; mi++) {
#pragma unroll
        for (int q = 0; q < 2; q++) {
            int gm = m0 + wm * 32 + mi * 16 + (lane >> 2) + q * 8;
            int i0 = gm >> 7, i1 = gm & 127;
#pragma unroll
            for (int nj = 0; nj < 4; nj++) {
                int gn = wn * 32 + nj * 8 + (lane & 3) * 2;
                float v0 = acc[mi][nj][q * 2 + 0];
                float v1 = acc[mi][nj][q * 2 + 1];
                if (EPI) {
                    v0 *= E0[i0 * NC + gn]     * E1[i1 * NC + gn];
                    v1 *= E0[i0 * NC + gn + 1] * E1[i1 * NC + gn + 1];
                    *(uint32_t*)&yout[(size_t)gm * NC + gn] =
                        pack_h2(__float2half(v0), __float2half(v1));
                } else {
                    *(float2*)&C[(size_t)gm * NC + gn] = make_float2(v0, v1);
                }
            }
        }
    }
}

// -------------------- launch -----------------------------------------------------
// Inputs: 0:x[V,C] 1:edge_index 2:L 3:mass[V] 4:evals0[64] 5:evals1[128]
//         6:evecs[V,V] 7:diffusion_time[2,C]   Output: [V,C] fp32
extern "C" void kernel_launch(void* const* d_in, const int* in_sizes, int n_in,
                              void* d_out, int out_size) {
    const float* x      = (const float*)d_in[0];
    const float* mass   = (const float*)d_in[3];
    const float* evals0 = (const float*)d_in[4];
    const float* evals1 = (const float*)d_in[5];
    const float* evecs  = (const float*)d_in[6];
    const float* dt     = (const float*)d_in[7];
    float* out          = (float*)d_out;

    __half *Eh, *xq, *yq;
    float *E0, *E1;
    cudaGetSymbolAddress((void**)&Eh, g_Eh);
    cudaGetSymbolAddress((void**)&xq, g_x);
    cudaGetSymbolAddress((void**)&yq, g_y);
    cudaGetSymbolAddress((void**)&E0, g_E0);
    cudaGetSymbolAddress((void**)&E1, g_E1);

    cudaFuncSetAttribute(gemm_kernel<1, 1>, cudaFuncAttributeMaxDynamicSharedMemorySize, SMEM_BYTES);
    cudaFuncSetAttribute(gemm_kernel<0, 0>, cudaFuncAttributeMaxDynamicSharedMemorySize, SMEM_BYTES);

    coef_kernel<<<192, 128>>>(evals0, evals1, dt);
    convE_kernel<<<2368, 256>>>((const float4*)evecs, (uint2*)Eh);
    prepx_kernel<<<NV * NC / 4 / 256, 256>>>((const float4*)x, mass, (uint2*)xq);

    // GEMM1: y = coef .* (E^T @ xw)
    gemm_kernel<1, 1><<<NV / BM, 256, SMEM_BYTES>>>(Eh, xq, nullptr, yq, E0, E1);
    // GEMM2: out = E @ y
    gemm_kernel<0, 0><<<NV / BM, 256, SMEM_BYTES>>>(Eh, yq, out, nullptr, nullptr, nullptr);
}

// round 13
// speedup vs baseline: 5.2599x; 1.0623x over previous
#include <cuda_runtime.h>
#include <cuda_fp16.h>
#include <cstdint>

#define NV 8192
#define NC 128

// -------------------- device scratch (no allocs allowed) --------------------
__device__ __half g_Eh[(size_t)NV * NV];   // E fp16, row-major
__device__ __half g_x[NV * NC];            // xw fp16
__device__ __half g_y[NV * NC];            // y  fp16
__device__ float g_part[2][NV * NC];       // split-K partials
__device__ float g_E0[64 * NC];
__device__ float g_E1[128 * NC];

// -------------------- small kernels ------------------------------------------
__global__ void coef_kernel(const float* __restrict__ ev0,
                            const float* __restrict__ ev1,
                            const float* __restrict__ dt) {
    int c = threadIdx.x;
    int b = blockIdx.x;
    if (b < 64) g_E0[b * NC + c] = __expf(-ev0[b] * dt[c]);
    else        g_E1[(b - 64) * NC + c] = __expf(-ev1[b - 64] * dt[NC + c]);
}

__device__ __forceinline__ uint32_t pack_h2(__half a, __half b) {
    __half2 p{a, b};
    return *(uint32_t*)&p;
}

// E fp32 -> fp16, 8 values per thread, 16B stores
__global__ void __launch_bounds__(256) convE_kernel(const float4* __restrict__ E4,
                                                    uint4* __restrict__ Eh) {
    const size_t N8 = (size_t)NV * NV / 8;
    for (size_t idx = (size_t)blockIdx.x * 256 + threadIdx.x; idx < N8;
         idx += (size_t)gridDim.x * 256) {
        float4 a = E4[idx * 2], b = E4[idx * 2 + 1];
        Eh[idx] = make_uint4(pack_h2(__float2half(a.x), __float2half(a.y)),
                             pack_h2(__float2half(a.z), __float2half(a.w)),
                             pack_h2(__float2half(b.x), __float2half(b.y)),
                             pack_h2(__float2half(b.z), __float2half(b.w)));
    }
}

// xw = x * mass -> fp16
__global__ void __launch_bounds__(256) prepx_kernel(const float4* __restrict__ x4,
                                                    const float* __restrict__ mass,
                                                    uint2* __restrict__ xq) {
    int idx = blockIdx.x * 256 + threadIdx.x;
    float m = mass[(idx * 4) >> 7];
    float4 v = x4[idx];
    xq[idx] = make_uint2(pack_h2(__float2half(v.x * m), __float2half(v.y * m)),
                         pack_h2(__float2half(v.z * m), __float2half(v.w * m)));
}

// reduce GEMM1 split-K partials, apply coef, emit fp16 y [V][C]
__global__ void __launch_bounds__(256) reduce1_kernel(const float4* __restrict__ P0,
                                                      const float4* __restrict__ P1,
                                                      uint2* __restrict__ y,
                                                      const float4* __restrict__ E0,
                                                      const float4* __restrict__ E1) {
    int idx = blockIdx.x * 256 + threadIdx.x;       // over NV*NC/4
    int gm = (idx * 4) >> 7;
    int gn4 = idx & 31;
    float4 a = P0[idx], b = P1[idx];
    float4 c0 = E0[(gm >> 7) * 32 + gn4];
    float4 c1 = E1[(gm & 127) * 32 + gn4];
    float v0 = (a.x + b.x) * c0.x * c1.x;
    float v1 = (a.y + b.y) * c0.y * c1.y;
    float v2 = (a.z + b.z) * c0.z * c1.z;
    float v3 = (a.w + b.w) * c0.w * c1.w;
    y[idx] = make_uint2(pack_h2(__float2half(v0), __float2half(v1)),
                        pack_h2(__float2half(v2), __float2half(v3)));
}

__global__ void __launch_bounds__(256) reduce2_kernel(const float4* __restrict__ P0,
                                                      const float4* __restrict__ P1,
                                                      float4* __restrict__ out) {
    int idx = blockIdx.x * 256 + threadIdx.x;
    float4 a = P0[idx], b = P1[idx];
    out[idx] = make_float4(a.x + b.x, a.y + b.y, a.z + b.z, a.w + b.w);
}

// -------------------- mma.sync helpers ----------------------------------------
__device__ __forceinline__ void ldsm4(uint32_t* r, uint32_t addr) {
    asm volatile("ldmatrix.sync.aligned.m8n8.x4.shared.b16 {%0,%1,%2,%3}, [%4];"
                 : "=r"(r[0]), "=r"(r[1]), "=r"(r[2]), "=r"(r[3]) : "r"(addr));
}
__device__ __forceinline__ void ldsm4t(uint32_t* r, uint32_t addr) {
    asm volatile("ldmatrix.sync.aligned.m8n8.x4.trans.shared.b16 {%0,%1,%2,%3}, [%4];"
                 : "=r"(r[0]), "=r"(r[1]), "=r"(r[2]), "=r"(r[3]) : "r"(addr));
}
__device__ __forceinline__ void mma16816(float* d, const uint32_t* a, const uint32_t* b) {
    asm volatile("mma.sync.aligned.m16n8k16.row.col.f32.f16.f16.f32 "
                 "{%0,%1,%2,%3}, {%4,%5,%6,%7}, {%8,%9}, {%0,%1,%2,%3};"
                 : "+f"(d[0]), "+f"(d[1]), "+f"(d[2]), "+f"(d[3])
                 : "r"(a[0]), "r"(a[1]), "r"(a[2]), "r"(a[3]),
                   "r"(b[0]), "r"(b[1]));
}
#define CP16(dst, src) \
    asm volatile("cp.async.cg.shared.global [%0], [%1], 16;" :: "r"(dst), "l"(src) : "memory")

// -------------------- GEMM config ----------------------------------------------
#define BM 64
#define BK 64
#define APAD 72                       // halves/row (144 B stride, mod128=16)
#define BPAD 136
#define A_BYTES  (BK * APAD * 2)      // 9216
#define B_BYTES  (BK * BPAD * 2)      // 17408
#define STAGE_BYTES (A_BYTES + B_BYTES)   // 26624
#define NSTAGE 3
#define SMEM_BYTES (NSTAGE * STAGE_BYTES) // 79872 -> 2 CTAs/SM

// Split-K partial: P[m,n] = sum_{k half} Aop[m,k]*B[k,n]; plain fp16.
// blockIdx.x = M tile, blockIdx.y = K half.
template <int TRANS_A>
__global__ void __launch_bounds__(256, 2)
gemm_kernel(const __half* __restrict__ A, const __half* __restrict__ B,
            float* __restrict__ P)
{
    extern __shared__ __half sm[];
    const uint32_t smbase = (uint32_t)__cvta_generic_to_shared(sm);
    const int tid  = threadIdx.x;
    const int lane = tid & 31, wid = tid >> 5;
    const int wm   = wid >> 2, wn = wid & 3;      // 2 x 4 warps (32x32 tiles)
    const int m0   = blockIdx.x * BM;
    const int kbase = blockIdx.y * (NV / 2);
    float* Pout = P + (size_t)blockIdx.y * NV * NC;

    auto issue = [&](int kt, int s) {
        const int k0 = kbase + kt * BK;
        const uint32_t sb = smbase + s * STAGE_BYTES;
#pragma unroll
        for (int i = 0; i < 2; i++) {             // A: 512 chunks
            int idx = i * 256 + tid;
            int r = idx >> 3, q = idx & 7;
            size_t ga = TRANS_A ? (size_t)(k0 + r) * NV + m0 + q * 8
                                : (size_t)(m0 + r) * NV + k0 + q * 8;
            CP16(sb + (uint32_t)(r * APAD + q * 8) * 2, (const void*)(A + ga));
        }
#pragma unroll
        for (int i = 0; i < 4; i++) {             // B: 1024 chunks
            int idx = i * 256 + tid;
            int r = idx >> 4, q = idx & 15;
            size_t gb = (size_t)(k0 + r) * NC + q * 8;
            CP16(sb + A_BYTES + (uint32_t)(r * BPAD + q * 8) * 2, (const void*)(B + gb));
        }
        asm volatile("cp.async.commit_group;" ::: "memory");
    };

    float acc[2][4][4];
#pragma unroll
    for (int a = 0; a < 2; a++)
#pragma unroll
        for (int b = 0; b < 4; b++)
#pragma unroll
            for (int q = 0; q < 4; q++) acc[a][b][q] = 0.0f;

    auto compute = [&](int s) {
        const uint32_t Ab = smbase + s * STAGE_BYTES;
        const uint32_t Bb = Ab + A_BYTES;
#pragma unroll
        for (int ks = 0; ks < 4; ks++) {
            uint32_t af[2][4], bf[2][4];
#pragma unroll
            for (int mi = 0; mi < 2; mi++) {
                if (TRANS_A) {
                    int krow = ks * 16 + (lane & 7) + ((lane >> 4) << 3);
                    int mcol = wm * 32 + mi * 16 + (lane & 8);
                    ldsm4t(af[mi], Ab + (uint32_t)(krow * APAD + mcol) * 2);
                } else {
                    int mrow = wm * 32 + mi * 16 + (lane & 15);
                    int kcol = ks * 16 + ((lane >> 4) << 3);
                    ldsm4(af[mi], Ab + (uint32_t)(mrow * APAD + kcol) * 2);
                }
            }
#pragma unroll
            for (int nj2 = 0; nj2 < 2; nj2++) {
                int krow = ks * 16 + (lane & 15);
                int ncol = wn * 32 + nj2 * 16 + ((lane >> 4) << 3);
                ldsm4t(bf[nj2], Bb + (uint32_t)(krow * BPAD + ncol) * 2);
            }
#pragma unroll
            for (int mi = 0; mi < 2; mi++)
#pragma unroll
                for (int nj = 0; nj < 4; nj++)
                    mma16816(acc[mi][nj], af[mi], &bf[nj >> 1][(nj & 1) * 2]);
        }
    };

    const int NIT = (NV / 2) / BK;   // 64
    issue(0, 0);
    issue(1, 1);
#pragma unroll 1
    for (int kt = 0; kt < NIT; kt++) {
        if (kt < NIT - 1) asm volatile("cp.async.wait_group 1;" ::: "memory");
        else              asm volatile("cp.async.wait_group 0;" ::: "memory");
        __syncthreads();
        compute(kt % NSTAGE);
        if (kt + 2 < NIT) issue(kt + 2, (kt + 2) % NSTAGE);
    }

    // ---- epilogue: fp32 partials ----
#pragma unroll
    for (int mi = 0; mi < 2; mi++) {
#pragma unroll
        for (int q = 0; q < 2; q++) {
            int gm = m0 + wm * 32 + mi * 16 + (lane >> 2) + q * 8;
#pragma unroll
            for (int nj = 0; nj < 4; nj++) {
                int gn = wn * 32 + nj * 8 + (lane & 3) * 2;
                *(float2*)&Pout[(size_t)gm * NC + gn] =
                    make_float2(acc[mi][nj][q * 2 + 0], acc[mi][nj][q * 2 + 1]);
            }
        }
    }
}

// -------------------- launch -----------------------------------------------------
// Inputs: 0:x[V,C] 1:edge_index 2:L 3:mass[V] 4:evals0[64] 5:evals1[128]
//         6:evecs[V,V] 7:diffusion_time[2,C]   Output: [V,C] fp32
extern "C" void kernel_launch(void* const* d_in, const int* in_sizes, int n_in,
                              void* d_out, int out_size) {
    const float* x      = (const float*)d_in[0];
    const float* mass   = (const float*)d_in[3];
    const float* evals0 = (const float*)d_in[4];
    const float* evals1 = (const float*)d_in[5];
    const float* evecs  = (const float*)d_in[6];
    const float* dt     = (const float*)d_in[7];
    float* out          = (float*)d_out;

    __half *Eh, *xq, *yq;
    float *P, *E0, *E1;
    cudaGetSymbolAddress((void**)&Eh, g_Eh);
    cudaGetSymbolAddress((void**)&xq, g_x);
    cudaGetSymbolAddress((void**)&yq, g_y);
    cudaGetSymbolAddress((void**)&P,  g_part);
    cudaGetSymbolAddress((void**)&E0, g_E0);
    cudaGetSymbolAddress((void**)&E1, g_E1);

    cudaFuncSetAttribute(gemm_kernel<1>, cudaFuncAttributeMaxDynamicSharedMemorySize, SMEM_BYTES);
    cudaFuncSetAttribute(gemm_kernel<0>, cudaFuncAttributeMaxDynamicSharedMemorySize, SMEM_BYTES);

    coef_kernel<<<192, 128>>>(evals0, evals1, dt);
    convE_kernel<<<2368, 256>>>((const float4*)evecs, (uint4*)Eh);
    prepx_kernel<<<NV * NC / 4 / 256, 256>>>((const float4*)x, mass, (uint2*)xq);

    const int NQ = NV * NC / 4 / 256;
    // GEMM1 partials: P = E^T @ xw (split-K)
    gemm_kernel<1><<<dim3(NV / BM, 2), 256, SMEM_BYTES>>>(Eh, xq, P);
    // y = coef .* (P0 + P1) -> fp16
    reduce1_kernel<<<NQ, 256>>>((const float4*)P, (const float4*)(P + NV * NC),
                                (uint2*)yq, (const float4*)E0, (const float4*)E1);
    // GEMM2 partials: P = E @ y (split-K)
    gemm_kernel<0><<<dim3(NV / BM, 2), 256, SMEM_BYTES>>>(Eh, yq, P);
    // out = P0 + P1
    reduce2_kernel<<<NQ, 256>>>((const float4*)P, (const float4*)(P + NV * NC), (float4*)out);
}